// round 3
// baseline (speedup 1.0000x reference)
#include <cuda_runtime.h>

// 3D Haar DWT: x (2,32,64,128,128) fp32 -> 8 subbands each (2,32,32,64,64),
// concatenated in order (LLL,LLH,LHL,LHH,HLL,HLH,HHL,HHH).
// R2: 2 p-positions per thread (p, p+32) -> deeper MLP, longer per-stream
// bursts, half the blocks. Still pure HBM streaming.

constexpr int IN_D = 64, IN_H = 128, IN_W = 128;
constexpr int OD = 32, OP = 64, OQ = 64;
constexpr int NC = 64;                          // N*C
constexpr long long SUB = (long long)NC * OD * OP * OQ;

__device__ __forceinline__ float4 f4add(float4 a, float4 b) {
    return make_float4(a.x + b.x, a.y + b.y, a.z + b.z, a.w + b.w);
}
__device__ __forceinline__ float4 f4sub(float4 a, float4 b) {
    return make_float4(a.x - b.x, a.y - b.y, a.z - b.z, a.w - b.w);
}
__device__ __forceinline__ float4 f4scale(float4 a, float s) {
    return make_float4(a.x * s, a.y * s, a.z * s, a.w * s);
}

struct WPair { float4 lo, hi; };

__device__ __forceinline__ WPair wsplit(float4 u, float4 v) {
    WPair r;
    r.lo = make_float4(u.x + u.y, u.z + u.w, v.x + v.y, v.z + v.w);
    r.hi = make_float4(u.x - u.y, u.z - u.w, v.x - v.y, v.z - v.w);
    return r;
}

// Process one 2x2x8 input block -> 8 float4 outputs, store to 8 subbands.
__device__ __forceinline__ void butterfly_store(
    float4 a0, float4 a1, float4 b0, float4 b1,
    float4 c0, float4 c1, float4 d0, float4 d1,
    float* __restrict__ outp, long long sub)
{
    WPair w00 = wsplit(a0, a1);
    WPair w01 = wsplit(b0, b1);
    WPair w10 = wsplit(c0, c1);
    WPair w11 = wsplit(d0, d1);

    float4 d0_ll = f4add(w00.lo, w01.lo);
    float4 d0_lh = f4add(w00.hi, w01.hi);
    float4 d0_hl = f4sub(w00.lo, w01.lo);
    float4 d0_hh = f4sub(w00.hi, w01.hi);
    float4 d1_ll = f4add(w10.lo, w11.lo);
    float4 d1_lh = f4add(w10.hi, w11.hi);
    float4 d1_hl = f4sub(w10.lo, w11.lo);
    float4 d1_hh = f4sub(w10.hi, w11.hi);

    const float s = 0.3535533905932738f;  // (1/sqrt(2))^3

    __stcs((float4*)(outp + 0 * sub), f4scale(f4add(d0_ll, d1_ll), s));
    __stcs((float4*)(outp + 1 * sub), f4scale(f4add(d0_lh, d1_lh), s));
    __stcs((float4*)(outp + 2 * sub), f4scale(f4add(d0_hl, d1_hl), s));
    __stcs((float4*)(outp + 3 * sub), f4scale(f4add(d0_hh, d1_hh), s));
    __stcs((float4*)(outp + 4 * sub), f4scale(f4sub(d0_ll, d1_ll), s));
    __stcs((float4*)(outp + 5 * sub), f4scale(f4sub(d0_lh, d1_lh), s));
    __stcs((float4*)(outp + 6 * sub), f4scale(f4sub(d0_hl, d1_hl), s));
    __stcs((float4*)(outp + 7 * sub), f4scale(f4sub(d0_hh, d1_hh), s));
}

__global__ void __launch_bounds__(256) dwt3d_haar_kernel(
    const float* __restrict__ x, float* __restrict__ out)
{
    int idx = blockIdx.x * 256 + threadIdx.x;
    // decode: q4 (16), p (32 -> handles p and p+32), r (32), nc (64)
    int q4 = idx & 15;
    int t  = idx >> 4;
    int p  = t & 31;
    t >>= 5;
    int r  = t & 31;
    int nc = t >> 5;

    const long long dstride = (long long)IN_H * IN_W;

    const float* baseA = x
        + (((long long)nc * IN_D + 2 * r) * IN_H + 2 * p) * IN_W
        + q4 * 8;
    const float* baseB = baseA + (long long)64 * IN_W;  // p + 32 -> h + 64

    // Front-batch all 16 loads (independent -> deep MLP).
    float4 Aa0 = __ldcs((const float4*)(baseA));
    float4 Aa1 = __ldcs((const float4*)(baseA) + 1);
    float4 Ab0 = __ldcs((const float4*)(baseA + IN_W));
    float4 Ab1 = __ldcs((const float4*)(baseA + IN_W) + 1);
    float4 Ac0 = __ldcs((const float4*)(baseA + dstride));
    float4 Ac1 = __ldcs((const float4*)(baseA + dstride) + 1);
    float4 Ad0 = __ldcs((const float4*)(baseA + dstride + IN_W));
    float4 Ad1 = __ldcs((const float4*)(baseA + dstride + IN_W) + 1);

    float4 Ba0 = __ldcs((const float4*)(baseB));
    float4 Ba1 = __ldcs((const float4*)(baseB) + 1);
    float4 Bb0 = __ldcs((const float4*)(baseB + IN_W));
    float4 Bb1 = __ldcs((const float4*)(baseB + IN_W) + 1);
    float4 Bc0 = __ldcs((const float4*)(baseB + dstride));
    float4 Bc1 = __ldcs((const float4*)(baseB + dstride) + 1);
    float4 Bd0 = __ldcs((const float4*)(baseB + dstride + IN_W));
    float4 Bd1 = __ldcs((const float4*)(baseB + dstride + IN_W) + 1);

    long long oA = (((long long)nc * OD + r) * OP + p) * OQ + q4 * 4;
    long long oB = oA + (long long)32 * OQ;  // p + 32

    butterfly_store(Aa0, Aa1, Ab0, Ab1, Ac0, Ac1, Ad0, Ad1, out + oA, SUB);
    butterfly_store(Ba0, Ba1, Bb0, Bb1, Bc0, Bc1, Bd0, Bd1, out + oB, SUB);
}

extern "C" void kernel_launch(void* const* d_in, const int* in_sizes, int n_in,
                              void* d_out, int out_size) {
    const float* x = (const float*)d_in[0];
    float* out = (float*)d_out;

    // threads: 64 * 32 * 32 * 16 = 1,048,576 -> 4096 blocks
    const int total = NC * OD * 32 * (OQ / 4);
    dwt3d_haar_kernel<<<total / 256, 256>>>(x, out);
}

// round 5
// speedup vs baseline: 1.0031x; 1.0031x over previous
#include <cuda_runtime.h>

// 3D Haar DWT: x (2,32,64,128,128) fp32 -> 8 subbands each (2,32,32,64,64),
// order (LLL,LLH,LHL,LHH,HLL,HLH,HHL,HHH).
// R4: L2 residency via legal sm_103a encodings:
//   - input loads: 256-bit ld.global.nc.L2::evict_last.v8.b32 (pin in L2
//     across graph replays; also halves LDG count)
//   - output stores: st.global.L2::cache_hint.v4.f32 with a fractional
//     evict_first policy (write stream passes through L2 without displacing
//     the pinned input)

constexpr int IN_D = 64, IN_H = 128, IN_W = 128;
constexpr int OD = 32, OP = 64, OQ = 64;
constexpr int NC = 64;                         // N*C
constexpr long long SUB = (long long)NC * OD * OP * OQ;

// 256-bit load of 8 consecutive floats, L2 evict_last.
__device__ __forceinline__ void ld8_evict_last(const float* p, float4& u, float4& v) {
    unsigned r0, r1, r2, r3, r4, r5, r6, r7;
    asm volatile(
        "ld.global.nc.L2::evict_last.v8.b32 {%0,%1,%2,%3,%4,%5,%6,%7}, [%8];"
        : "=r"(r0), "=r"(r1), "=r"(r2), "=r"(r3),
          "=r"(r4), "=r"(r5), "=r"(r6), "=r"(r7)
        : "l"(p));
    u = make_float4(__uint_as_float(r0), __uint_as_float(r1),
                    __uint_as_float(r2), __uint_as_float(r3));
    v = make_float4(__uint_as_float(r4), __uint_as_float(r5),
                    __uint_as_float(r6), __uint_as_float(r7));
}

// 128-bit store with evict_first policy via cache_hint.
__device__ __forceinline__ void st4_evict_first(float4* p, float4 v) {
    asm volatile(
        "{\n\t"
        ".reg .b64 pol;\n\t"
        "createpolicy.fractional.L2::evict_first.b64 pol, 1.0;\n\t"
        "st.global.L2::cache_hint.v4.f32 [%0], {%1,%2,%3,%4}, pol;\n\t"
        "}"
        :: "l"(p), "f"(v.x), "f"(v.y), "f"(v.z), "f"(v.w)
        : "memory");
}

__device__ __forceinline__ float4 f4add(float4 a, float4 b) {
    return make_float4(a.x + b.x, a.y + b.y, a.z + b.z, a.w + b.w);
}
__device__ __forceinline__ float4 f4sub(float4 a, float4 b) {
    return make_float4(a.x - b.x, a.y - b.y, a.z - b.z, a.w - b.w);
}
__device__ __forceinline__ float4 f4scale(float4 a, float s) {
    return make_float4(a.x * s, a.y * s, a.z * s, a.w * s);
}

struct WPair { float4 lo, hi; };

__device__ __forceinline__ WPair wsplit(float4 u, float4 v) {
    WPair r;
    r.lo = make_float4(u.x + u.y, u.z + u.w, v.x + v.y, v.z + v.w);
    r.hi = make_float4(u.x - u.y, u.z - u.w, v.x - v.y, v.z - v.w);
    return r;
}

__global__ void __launch_bounds__(256) dwt3d_haar_kernel(
    const float* __restrict__ x, float* __restrict__ out)
{
    int idx = blockIdx.x * 256 + threadIdx.x;
    // decode: q4 (16), p (64), r (32), nc (64)
    int q4 = idx & 15;
    int t  = idx >> 4;
    int p  = t & 63;
    t >>= 6;
    int r  = t & 31;
    int nc = t >> 5;

    const float* base = x
        + (((long long)nc * IN_D + 2 * r) * IN_H + 2 * p) * IN_W
        + q4 * 8;

    float4 a0, a1, b0, b1, c0, c1, d0, d1;
    ld8_evict_last(base,                         a0, a1);  // d=0, h=0
    ld8_evict_last(base + IN_W,                  b0, b1);  // d=0, h=1
    ld8_evict_last(base + IN_H * IN_W,           c0, c1);  // d=1, h=0
    ld8_evict_last(base + IN_H * IN_W + IN_W,    d0, d1);  // d=1, h=1

    // Stage 1: w-axis butterflies
    WPair w00 = wsplit(a0, a1);
    WPair w01 = wsplit(b0, b1);
    WPair w10 = wsplit(c0, c1);
    WPair w11 = wsplit(d0, d1);

    // Stage 2: h-axis butterflies
    float4 d0_ll = f4add(w00.lo, w01.lo);
    float4 d0_lh = f4add(w00.hi, w01.hi);
    float4 d0_hl = f4sub(w00.lo, w01.lo);
    float4 d0_hh = f4sub(w00.hi, w01.hi);
    float4 d1_ll = f4add(w10.lo, w11.lo);
    float4 d1_lh = f4add(w10.hi, w11.hi);
    float4 d1_hl = f4sub(w10.lo, w11.lo);
    float4 d1_hh = f4sub(w10.hi, w11.hi);

    // Stage 3: d-axis butterflies + scale
    const float s = 0.3535533905932738f;  // (1/sqrt(2))^3

    float4 o0 = f4scale(f4add(d0_ll, d1_ll), s);
    float4 o1 = f4scale(f4add(d0_lh, d1_lh), s);
    float4 o2 = f4scale(f4add(d0_hl, d1_hl), s);
    float4 o3 = f4scale(f4add(d0_hh, d1_hh), s);
    float4 o4 = f4scale(f4sub(d0_ll, d1_ll), s);
    float4 o5 = f4scale(f4sub(d0_lh, d1_lh), s);
    float4 o6 = f4scale(f4sub(d0_hl, d1_hl), s);
    float4 o7 = f4scale(f4sub(d0_hh, d1_hh), s);

    long long o = (((long long)nc * OD + r) * OP + p) * OQ + q4 * 4;
    float4* outp = (float4*)(out + o);
    const long long sub4 = SUB / 4;

    st4_evict_first(outp + 0 * sub4, o0);
    st4_evict_first(outp + 1 * sub4, o1);
    st4_evict_first(outp + 2 * sub4, o2);
    st4_evict_first(outp + 3 * sub4, o3);
    st4_evict_first(outp + 4 * sub4, o4);
    st4_evict_first(outp + 5 * sub4, o5);
    st4_evict_first(outp + 6 * sub4, o6);
    st4_evict_first(outp + 7 * sub4, o7);
}

extern "C" void kernel_launch(void* const* d_in, const int* in_sizes, int n_in,
                              void* d_out, int out_size) {
    const float* x = (const float*)d_in[0];
    float* out = (float*)d_out;

    const int total = NC * OD * OP * (OQ / 4);  // 2,097,152 threads
    dwt3d_haar_kernel<<<total / 256, 256>>>(x, out);
}